// round 14
// baseline (speedup 1.0000x reference)
#include <cuda_runtime.h>
#include <cstddef>

// Shapes fixed by the problem
#define Nn 8
#define Cc 128
#define Tt 32
#define HWp 784                        // 28*28
#define TOTAL ((size_t)Nn*Cc*Tt*HWp)   // 25,690,112 floats

#define AGRID 148                      // guard kernel: cheapest measured exit

// ---------------------------------------------------------------------------
// Structure:
//   node 1: cudaMemcpyAsync D2D  out <- x   (copy-engine path; R13 decompose
//           shows ~28 us for the 205 MB r+w, ~7.3 TB/s — faster than any SM
//           copy variant we measured, which converged at ~31 us).
//   node 2: guarded attention kernel, grid=148 (R7-measured cheapest guard
//           drain: 4.1 us vs 7.5 us at grid 1024).
//           alpha==0 (this benchmark): load alpha + exit.
//           alpha!=0: grid-stride over the 1024 (n,c) tiles; each block
//           independently computes the full energy matrix for its n
//           (redundant recompute -> block-local, no grid barrier, no global
//           scratch), softmaxes it, adds alpha * attn @ x into its tile
//           (out already holds x from the memcpy).  Tiles are disjoint.
// ---------------------------------------------------------------------------
__global__ void __launch_bounds__(256, 8) attention_kernel(
        const float* __restrict__ x, const float* __restrict__ alpha,
        float* __restrict__ out) {
    const float a = __ldg(alpha);
    if (a == 0.0f) return;             // attention term contributes exactly 0

    const int tid = threadIdx.x;
    // Overlaid buffer: phase 1 tile(t,j)=buf[t*33+j]; phase 2 attn matrix.
    __shared__ float buf[Tt * 33];             // 4224 B

    for (int nc = blockIdx.x; nc < Nn * Cc; nc += AGRID) {
        const int n = nc >> 7;                 // nc / Cc
        __syncthreads();                       // buf reuse across nc iters

        // Full energy for this n: E[t][s] = sum_c sum_hw x[n,c,t,hw]*x[n,c,s,hw]
        float acc[4] = {0.f, 0.f, 0.f, 0.f};
        for (int c = 0; c < Cc; c++) {
            const float* __restrict__ A =
                x + ((size_t)n * Cc + c) * (Tt * HWp);
            for (int hw0 = 0; hw0 < HWp; hw0 += 32) {
                for (int e = tid; e < Tt * 32; e += 256) {
                    int t = e >> 5, j = e & 31;
                    int hw = hw0 + j;
                    buf[t * 33 + j] = (hw < HWp) ? A[t * HWp + hw] : 0.0f;
                }
                __syncthreads();
                #pragma unroll
                for (int k = 0; k < 4; k++) {
                    int p = tid + k * 256;      // (t,s) pair 0..1023
                    int t = p >> 5, s = p & 31;
                    float v = 0.f;
                    #pragma unroll
                    for (int j = 0; j < 32; j++)
                        v = fmaf(buf[t * 33 + j], buf[s * 33 + j], v);
                    acc[k] += v;
                }
                __syncthreads();
            }
        }
        #pragma unroll
        for (int k = 0; k < 4; k++) {
            int p = tid + k * 256;
            buf[(p >> 5) * 33 + (p & 31)] = acc[k];
        }
        __syncthreads();

        // Row softmax: 8 warps, rows t = w, w+8, w+16, w+24
        {
            const int lane = tid & 31, w = tid >> 5;
            #pragma unroll
            for (int r = 0; r < 4; r++) {
                int t = w + r * 8;
                float v = buf[t * 33 + lane];
                float m = v;
                #pragma unroll
                for (int o = 16; o > 0; o >>= 1)
                    m = fmaxf(m, __shfl_xor_sync(0xffffffffu, m, o));
                float p = __expf(v - m);
                float ssum = p;
                #pragma unroll
                for (int o = 16; o > 0; o >>= 1)
                    ssum += __shfl_xor_sync(0xffffffffu, ssum, o);
                buf[t * 33 + lane] = p / ssum;
            }
        }
        __syncthreads();

        // out tile already holds x (memcpy): add the attention term.
        {
            const float* __restrict__ A = x   + (size_t)nc * (Tt * HWp);
            float* __restrict__       O = out + (size_t)nc * (Tt * HWp);
            for (int hw = tid; hw < HWp; hw += 256) {
                #pragma unroll 4
                for (int t = 0; t < Tt; t++) {
                    float s_acc = 0.f;
                    #pragma unroll
                    for (int s = 0; s < Tt; s++)
                        s_acc = fmaf(buf[t * 33 + s], A[s * HWp + hw], s_acc);
                    O[t * HWp + hw] += a * s_acc;
                }
            }
        }
    }
}

// ---------------------------------------------------------------------------
extern "C" void kernel_launch(void* const* d_in, const int* in_sizes, int n_in,
                              void* d_out, int out_size) {
    const float* x     = (const float*)d_in[0];
    const float* alpha = (const float*)d_in[1];
    if (n_in >= 2 && in_sizes[0] == 1) {   // defensive order swap
        x     = (const float*)d_in[1];
        alpha = (const float*)d_in[0];
    }
    float* out = (float*)d_out;

    // Node 1: D2D copy — copy-engine path, ~7.3 TB/s effective (R13).
    cudaMemcpyAsync(out, x, TOTAL * sizeof(float),
                    cudaMemcpyDeviceToDevice);

    // Node 2: guarded attention add (no-op when alpha == 0), cheapest-drain
    // grid shape.
    attention_kernel<<<AGRID, 256>>>(x, alpha, out);
}

// round 15
// speedup vs baseline: 1.0906x; 1.0906x over previous
#include <cuda_runtime.h>
#include <cstddef>

// Shapes fixed by the problem
#define Nn 8
#define Cc 128
#define Tt 32
#define HWp 784                        // 28*28
#define TOTAL ((size_t)Nn*Cc*Tt*HWp)   // 25,690,112 floats
#define N4    (TOTAL/4)                // 6,422,528 float4

#define BLK       256
#define CP_GRID   12544                // 2 x float4 per thread; N4 = 2*STRD
#define COLD_GRID (Nn*Cc)              // 1024 attention tile blocks
#define GRID      (CP_GRID + COLD_GRID)
#define STRD      ((size_t)CP_GRID * BLK)   // 3,211,264

// ---------------------------------------------------------------------------
// ONE kernel, ONE graph node, split grid (proven R10 structure; 35.3 us).
// This round isolates CTA granularity: 2 float4/thread, 2x the one-shot
// CTAs.  One-shot small CTAs have been the best SM-copy shape in every
// measurement (churn keeps fresh front-batched LDG.128 streaming into the
// LSU); this doubles the churn rate.
//
//   blocks [0, CP_GRID):  copy blocks (alpha==0 path): 2 x LDG.128 front-
//                         batched, 2 x STG.128 streaming, exit.
//   blocks [CP_GRID, +1024): attention blocks (alpha!=0 path): block nc
//                         independently computes the full energy for its n
//                         (redundant recompute -> no barrier, no scratch),
//                         softmax, out = x + alpha * attn @ x on its tile.
// Writers disjoint for either alpha value -> deterministic, race-free.
// ---------------------------------------------------------------------------
__global__ void __launch_bounds__(BLK, 8) fused_kernel(
        const float* __restrict__ x, const float* __restrict__ alpha,
        float* __restrict__ out) {
    const float a = __ldg(alpha);

    if (blockIdx.x < CP_GRID) {
        if (a != 0.0f) return;         // attention blocks will write out
        const float4* __restrict__ x4 = (const float4*)x;
        float4* __restrict__       o4 = (float4*)out;
        const size_t i = (size_t)blockIdx.x * BLK + threadIdx.x;
        float4 v0 = __ldcs(x4 + i);
        float4 v1 = __ldcs(x4 + i + STRD);
        __stcs(o4 + i,        v0);
        __stcs(o4 + i + STRD, v1);
        return;
    }

    // ================== attention blocks (cold) ==================
    if (a == 0.0f) return;             // copy blocks already wrote out

    const int nc = blockIdx.x - CP_GRID;      // 0..1023
    const int n  = nc >> 7;                   // nc / Cc
    const int tid = threadIdx.x;

    // Overlaid buffer: phase 1 tile(t,j)=buf[t*33+j]; phase 2 attn matrix.
    __shared__ float buf[Tt * 33];            // 4224 B

    // Full energy for this n: E[t][s] = sum_c sum_hw x[n,c,t,hw]*x[n,c,s,hw]
    float acc[4] = {0.f, 0.f, 0.f, 0.f};
    for (int c = 0; c < Cc; c++) {
        const float* __restrict__ A =
            x + ((size_t)n * Cc + c) * (Tt * HWp);
        for (int hw0 = 0; hw0 < HWp; hw0 += 32) {
            for (int e = tid; e < Tt * 32; e += BLK) {
                int t = e >> 5, j = e & 31;
                int hw = hw0 + j;
                buf[t * 33 + j] = (hw < HWp) ? A[t * HWp + hw] : 0.0f;
            }
            __syncthreads();
            #pragma unroll
            for (int k = 0; k < 4; k++) {
                int p = tid + k * BLK;         // (t,s) pair 0..1023
                int t = p >> 5, s = p & 31;
                float v = 0.f;
                #pragma unroll
                for (int j = 0; j < 32; j++)
                    v = fmaf(buf[t * 33 + j], buf[s * 33 + j], v);
                acc[k] += v;
            }
            __syncthreads();
        }
    }
    #pragma unroll
    for (int k = 0; k < 4; k++) {
        int p = tid + k * BLK;
        buf[(p >> 5) * 33 + (p & 31)] = acc[k];
    }
    __syncthreads();

    // Row softmax: 8 warps, rows t = w, w+8, w+16, w+24
    {
        const int lane = tid & 31, w = tid >> 5;
        #pragma unroll
        for (int r = 0; r < 4; r++) {
            int t = w + r * 8;
            float v = buf[t * 33 + lane];
            float m = v;
            #pragma unroll
            for (int o = 16; o > 0; o >>= 1)
                m = fmaxf(m, __shfl_xor_sync(0xffffffffu, m, o));
            float p = __expf(v - m);
            float ssum = p;
            #pragma unroll
            for (int o = 16; o > 0; o >>= 1)
                ssum += __shfl_xor_sync(0xffffffffu, ssum, o);
            buf[t * 33 + lane] = p / ssum;
        }
    }
    __syncthreads();

    // Write this block's tile: out = x + a * attn @ x
    {
        const float* __restrict__ A = x   + (size_t)nc * (Tt * HWp);
        float* __restrict__       O = out + (size_t)nc * (Tt * HWp);
        for (int hw = tid; hw < HWp; hw += BLK) {
            #pragma unroll 4
            for (int t = 0; t < Tt; t++) {
                float s_acc = 0.f;
                #pragma unroll
                for (int s = 0; s < Tt; s++)
                    s_acc = fmaf(buf[t * 33 + s], A[s * HWp + hw], s_acc);
                O[t * HWp + hw] = fmaf(a, s_acc, A[t * HWp + hw]);
            }
        }
    }
}

// ---------------------------------------------------------------------------
extern "C" void kernel_launch(void* const* d_in, const int* in_sizes, int n_in,
                              void* d_out, int out_size) {
    const float* x     = (const float*)d_in[0];
    const float* alpha = (const float*)d_in[1];
    if (n_in >= 2 && in_sizes[0] == 1) {   // defensive order swap
        x     = (const float*)d_in[1];
        alpha = (const float*)d_in[0];
    }
    float* out = (float*)d_out;

    fused_kernel<<<GRID, BLK>>>(x, alpha, out);
}